// round 1
// baseline (speedup 1.0000x reference)
#include <cuda_runtime.h>

// ---------------------------------------------------------------------------
// Swin shifted-window attention, fp32 SIMT baseline.
//   B=4, DIM=192, HEADS=6, HD=32, H=W=256, WS=8, SS=4
//   windows: 32x32 per image -> 4096 windows total, 64 tokens each
// Pipeline:
//   k0a/k0b: transpose qkv_w / proj_w  (coalesced GEMM B tiles later)
//   k1: fused shift+window-gather + QKV GEMM (scale folded into Q)
//   k2: per (window, head) attention: S = qK^T + rpb + shiftmask, softmax, O=SV
//   k3: proj GEMM + bias, fused reverse-partition + reverse-shift NCHW store
// ---------------------------------------------------------------------------

#define DIM    192
#define HEADS  6
#define HD     32
#define WS     8
#define SHIFT  4
#define NTOK   64          // tokens per window
#define BATCH  4
#define IMG    256
#define NWH    32          // windows per image side
#define NWIN   4096        // BATCH * 32 * 32
#define QSCALE 0.17677669529663687f   // 32^-0.5

// scratch (805 MB total, zero-init bss; allocation-free per harness rules)
__device__ float g_wqkvT[DIM * 3 * DIM];          // [192][576]
__device__ float g_wprojT[DIM * DIM];             // [192][192]
__device__ float g_q[NWIN * HEADS * NTOK * HD];   // [win][head][t][d], pre-scaled
__device__ float g_k[NWIN * HEADS * NTOK * HD];
__device__ float g_v[NWIN * HEADS * NTOK * HD];
__device__ float g_ao[NWIN * NTOK * DIM];         // attention out, [win][t][head*32+d]

// ---------------------------------------------------------------- transposes
__global__ void tr_qkv_kernel(const float* __restrict__ w) {
    int i = blockIdx.x * 256 + threadIdx.x;
    if (i < 576 * 192) {
        int r = i / 192, c = i - r * 192;
        g_wqkvT[c * 576 + r] = w[i];
    }
}
__global__ void tr_proj_kernel(const float* __restrict__ w) {
    int i = blockIdx.x * 256 + threadIdx.x;
    if (i < 192 * 192) {
        int r = i / 192, c = i - r * 192;
        g_wprojT[c * 192 + r] = w[i];
    }
}

// ---------------------------------------------------------------- QKV GEMM
// One block per window. A = gathered x tile [K=192][M=64] in smem,
// B = weight tile [K=192][N=64], 9 N-tiles. 4x4 micro-tile per thread.
__global__ __launch_bounds__(256, 2)
void qkv_kernel(const float* __restrict__ x, const float* __restrict__ qkv_b) {
    extern __shared__ float sm[];
    float* As = sm;              // [192][64]
    float* Bs = sm + 192 * 64;   // [192][64]

    const int win = blockIdx.x;
    const int b   = win >> 10;
    const int wi  = win & 1023;
    const int wh  = wi >> 5;
    const int wc  = wi & 31;
    const int tid = threadIdx.x;

    // gather shifted-window x into As[c][t]
    for (int i = tid; i < 192 * 64; i += 256) {
        int c = i >> 6, t = i & 63;
        int ti = t >> 3, tj = t & 7;
        int h = (wh * 8 + ti + SHIFT) & 255;
        int w = (wc * 8 + tj + SHIFT) & 255;
        As[i] = x[((b * DIM + c) << 16) + (h << 8) + w];
    }

    const int tx = tid & 15, ty = tid >> 4;
    const int m0 = ty * 4, n0 = tx * 4;

    for (int ntile = 0; ntile < 9; ntile++) {
        __syncthreads();
        for (int i = tid; i < 192 * 64; i += 256) {
            int k = i >> 6, n = i & 63;
            Bs[i] = g_wqkvT[k * 576 + ntile * 64 + n];
        }
        __syncthreads();

        float acc[4][4] = {};
        #pragma unroll 4
        for (int k = 0; k < 192; k++) {
            float4 a  = *(const float4*)(As + k * 64 + m0);
            float4 bv = *(const float4*)(Bs + k * 64 + n0);
            acc[0][0] += a.x * bv.x; acc[0][1] += a.x * bv.y; acc[0][2] += a.x * bv.z; acc[0][3] += a.x * bv.w;
            acc[1][0] += a.y * bv.x; acc[1][1] += a.y * bv.y; acc[1][2] += a.y * bv.z; acc[1][3] += a.y * bv.w;
            acc[2][0] += a.z * bv.x; acc[2][1] += a.z * bv.y; acc[2][2] += a.z * bv.z; acc[2][3] += a.z * bv.w;
            acc[3][0] += a.w * bv.x; acc[3][1] += a.w * bv.y; acc[3][2] += a.w * bv.z; acc[3][3] += a.w * bv.w;
        }

        const int cbase = ntile * 64 + n0;
        const int sel   = cbase / 192;               // 0=q, 1=k, 2=v (tiles never straddle)
        float* dst = (sel == 0) ? g_q : ((sel == 1) ? g_k : g_v);
        #pragma unroll
        for (int j = 0; j < 4; j++) {
            int c    = cbase + j;
            int head = (c - sel * 192) >> 5;
            int d    = c & 31;
            float bias = qkv_b[c];
            #pragma unroll
            for (int i2 = 0; i2 < 4; i2++) {
                float v = acc[i2][j] + bias;
                if (sel == 0) v *= QSCALE;
                dst[((win * HEADS + head) * NTOK + (m0 + i2)) * HD + d] = v;
            }
        }
    }
}

// ---------------------------------------------------------------- attention
// One block per (window, head). 256 threads.
__global__ __launch_bounds__(256, 4)
void attn_kernel(const float* __restrict__ rpb) {
    __shared__ __align__(16) float qs[32 * 68];  // qT [d][t], pad 68
    __shared__ __align__(16) float ks[32 * 68];  // kT [d][t]
    __shared__ __align__(16) float vs[64 * 32];  // v  [t][d]
    __shared__ __align__(16) float ss[64 * 68];  // scores [q][k], pad 68
    __shared__ float rb[225];

    const int bid  = blockIdx.x;
    const int win  = bid / 6;
    const int head = bid - win * 6;
    const int wi   = win & 1023;
    const int wh   = wi >> 5;
    const int wc   = wi & 31;
    const int tid  = threadIdx.x;

    const int base = (win * HEADS + head) * NTOK * HD;
    for (int i = tid; i < NTOK * HD; i += 256) {
        int t = i >> 5, d = i & 31;
        qs[d * 68 + t] = g_q[base + i];
        ks[d * 68 + t] = g_k[base + i];
        vs[i]          = g_v[base + i];
    }
    for (int i = tid; i < 225; i += 256) rb[i] = rpb[i * 6 + head];
    __syncthreads();

    // S = q^T k  (4x4 micro-tile)
    const int tx = tid & 15, ty = tid >> 4;
    const int m0 = ty * 4, n0 = tx * 4;
    float acc[4][4] = {};
    #pragma unroll
    for (int d = 0; d < 32; d++) {
        float4 a  = *(const float4*)(qs + d * 68 + m0);
        float4 bv = *(const float4*)(ks + d * 68 + n0);
        acc[0][0] += a.x * bv.x; acc[0][1] += a.x * bv.y; acc[0][2] += a.x * bv.z; acc[0][3] += a.x * bv.w;
        acc[1][0] += a.y * bv.x; acc[1][1] += a.y * bv.y; acc[1][2] += a.y * bv.z; acc[1][3] += a.y * bv.w;
        acc[2][0] += a.z * bv.x; acc[2][1] += a.z * bv.y; acc[2][2] += a.z * bv.z; acc[2][3] += a.z * bv.w;
        acc[3][0] += a.w * bv.x; acc[3][1] += a.w * bv.y; acc[3][2] += a.w * bv.z; acc[3][3] += a.w * bv.w;
    }

    // region labels for shifted-window mask (only boundary windows nonzero)
    int lq[4], lk[4];
    #pragma unroll
    for (int i = 0; i < 4; i++) {
        int m = m0 + i; int ti = m >> 3, tj = m & 7;
        lq[i] = ((wh == 31) ? ((ti < 4) ? 1 : 2) : 0) * 3
              + ((wc == 31) ? ((tj < 4) ? 1 : 2) : 0);
        int n = n0 + i; int ki = n >> 3, kj = n & 7;
        lk[i] = ((wh == 31) ? ((ki < 4) ? 1 : 2) : 0) * 3
              + ((wc == 31) ? ((kj < 4) ? 1 : 2) : 0);
    }
    #pragma unroll
    for (int i = 0; i < 4; i++) {
        int m = m0 + i;
        #pragma unroll
        for (int j = 0; j < 4; j++) {
            int n = n0 + j;
            int rel = ((m >> 3) - (n >> 3) + 7) * 15 + ((m & 7) - (n & 7) + 7);
            float v = acc[i][j] + rb[rel];
            if (lq[i] != lk[j]) v -= 100.0f;
            ss[m * 68 + n] = v;
        }
    }
    __syncthreads();

    // softmax: 4 lanes per row
    {
        const int row = tid >> 2, l4 = tid & 3;
        float vals[16];
        float mx = -1e30f;
        #pragma unroll
        for (int t = 0; t < 16; t++) {
            vals[t] = ss[row * 68 + l4 + 4 * t];
            mx = fmaxf(mx, vals[t]);
        }
        mx = fmaxf(mx, __shfl_xor_sync(0xffffffffu, mx, 1));
        mx = fmaxf(mx, __shfl_xor_sync(0xffffffffu, mx, 2));
        float sum = 0.f;
        #pragma unroll
        for (int t = 0; t < 16; t++) { vals[t] = __expf(vals[t] - mx); sum += vals[t]; }
        sum += __shfl_xor_sync(0xffffffffu, sum, 1);
        sum += __shfl_xor_sync(0xffffffffu, sum, 2);
        float inv = 1.0f / sum;
        #pragma unroll
        for (int t = 0; t < 16; t++) ss[row * 68 + l4 + 4 * t] = vals[t] * inv;
    }
    __syncthreads();

    // O = P V   (4x2 micro-tile over 64x32 output)
    const int n0b = tx * 2;
    float o[4][2] = {};
    for (int c = 0; c < 64; c++) {
        float b0 = vs[c * 32 + n0b];
        float b1 = vs[c * 32 + n0b + 1];
        #pragma unroll
        for (int i = 0; i < 4; i++) {
            float a = ss[(m0 + i) * 68 + c];
            o[i][0] += a * b0;
            o[i][1] += a * b1;
        }
    }
    #pragma unroll
    for (int i = 0; i < 4; i++) {
        #pragma unroll
        for (int j = 0; j < 2; j++) {
            g_ao[(win * NTOK + m0 + i) * DIM + head * HD + n0b + j] = o[i][j];
        }
    }
}

// ---------------------------------------------------------------- proj GEMM
// One block per window; fused bias + reverse partition + reverse shift store.
__global__ __launch_bounds__(256, 2)
void proj_kernel(const float* __restrict__ proj_b, float* __restrict__ out) {
    extern __shared__ float sm[];
    float* As = sm;               // [192][68]  (padded)
    float* Bs = sm + 192 * 68;    // [192][64]

    const int win = blockIdx.x;
    const int b   = win >> 10;
    const int wi  = win & 1023;
    const int wh  = wi >> 5;
    const int wc  = wi & 31;
    const int tid = threadIdx.x;

    for (int i = tid; i < 64 * 192; i += 256) {
        int t = i / 192, c = i - t * 192;       // coalesced gmem read
        As[c * 68 + t] = g_ao[win * 64 * 192 + i];
    }

    const int tx = tid & 15, ty = tid >> 4;
    const int m0 = ty * 4, n0 = tx * 4;

    for (int ntile = 0; ntile < 3; ntile++) {
        __syncthreads();
        for (int i = tid; i < 192 * 64; i += 256) {
            int k = i >> 6, n = i & 63;
            Bs[i] = g_wprojT[k * 192 + ntile * 64 + n];
        }
        __syncthreads();

        float acc[4][4] = {};
        #pragma unroll 4
        for (int k = 0; k < 192; k++) {
            float4 a  = *(const float4*)(As + k * 68 + m0);
            float4 bv = *(const float4*)(Bs + k * 64 + n0);
            acc[0][0] += a.x * bv.x; acc[0][1] += a.x * bv.y; acc[0][2] += a.x * bv.z; acc[0][3] += a.x * bv.w;
            acc[1][0] += a.y * bv.x; acc[1][1] += a.y * bv.y; acc[1][2] += a.y * bv.z; acc[1][3] += a.y * bv.w;
            acc[2][0] += a.z * bv.x; acc[2][1] += a.z * bv.y; acc[2][2] += a.z * bv.z; acc[2][3] += a.z * bv.w;
            acc[3][0] += a.w * bv.x; acc[3][1] += a.w * bv.y; acc[3][2] += a.w * bv.z; acc[3][3] += a.w * bv.w;
        }

        #pragma unroll
        for (int j = 0; j < 4; j++) {
            int c = ntile * 64 + n0 + j;
            float bias = proj_b[c];
            #pragma unroll
            for (int i2 = 0; i2 < 4; i2++) {
                int m = m0 + i2;
                int ti = m >> 3, tj = m & 7;
                int h = (wh * 8 + ti + SHIFT) & 255;   // reverse cyclic shift
                int w = (wc * 8 + tj + SHIFT) & 255;
                out[((b * DIM + c) << 16) + (h << 8) + w] = acc[i2][j] + bias;
            }
        }
    }
}

// ---------------------------------------------------------------- launch
extern "C" void kernel_launch(void* const* d_in, const int* in_sizes, int n_in,
                              void* d_out, int out_size) {
    const float* x      = (const float*)d_in[0];
    const float* qkv_w  = (const float*)d_in[1];
    const float* qkv_b  = (const float*)d_in[2];
    const float* proj_w = (const float*)d_in[3];
    const float* proj_b = (const float*)d_in[4];
    const float* rpb    = (const float*)d_in[5];
    float* out = (float*)d_out;

    tr_qkv_kernel<<<(576 * 192 + 255) / 256, 256>>>(qkv_w);
    tr_proj_kernel<<<(192 * 192 + 255) / 256, 256>>>(proj_w);

    const int smem_qkv  = (192 * 64 + 192 * 64) * 4;   // 96 KB
    const int smem_proj = (192 * 68 + 192 * 64) * 4;   // ~99 KB
    cudaFuncSetAttribute(qkv_kernel,  cudaFuncAttributeMaxDynamicSharedMemorySize, smem_qkv);
    cudaFuncSetAttribute(proj_kernel, cudaFuncAttributeMaxDynamicSharedMemorySize, smem_proj);

    qkv_kernel<<<NWIN, 256, smem_qkv>>>(x, qkv_b);
    attn_kernel<<<NWIN * HEADS, 256>>>(rpb);
    proj_kernel<<<NWIN, 256, smem_proj>>>(proj_b, out);
}

// round 5
// speedup vs baseline: 1.8637x; 1.8637x over previous
#include <cuda_runtime.h>
#include <cuda_bf16.h>
#include <cstdint>

// ---------------------------------------------------------------------------
// Swin shifted-window attention on GB300 (compute_103 toolchain: no tcgen05,
// so the tensor pipe is reached via mma.sync HMMA + ldmatrix).
//   B=4, DIM=192, HEADS=6, HD=32, H=W=256, WS=8, SS=4 -> 4096 windows x 64 tok
// Pipeline:
//   prep_bq / prep_bp : split fp32 weights into bf16 hi|lo tables [n][384]
//   qkv_mma : bf16 split-K GEMM (M=128 = 2 windows, split-K=576, N=9x64)
//             fused shift+window gather, bias, q-scale -> g_q/g_k/g_v
//   attn    : fp32 SIMT per (window, head) -- known-good round-1 kernel
//   proj_mma: bf16 split-K GEMM (M=128, split-K=576, N=3x64)
//             fused bias + reverse partition + reverse shift NCHW store
// Split precision: C = Ah*Bh + Al*Bh + Ah*Bl  (error ~3e-5 << 1e-3 gate)
// ---------------------------------------------------------------------------

#define DIM    192
#define HEADS  6
#define SHIFT  4
#define NWIN   4096
#define QSCALE 0.17677669529663687f

#define LDA 200          // A row pitch in bf16 elems (192 + 8): 400B, 16B-phase
#define LDB 200
// smem byte offsets (dynamic smem, 16B aligned)
#define AH_B 0           // Ah [128][200] bf16
#define AL_B 51200       // Al
#define BH_B 102400      // Bh [64][200]
#define BL_B 128000      // Bl
#define SM_BYTES 153600

// ---------------- scratch ---------------------------------------------------
__device__ __nv_bfloat16 g_bq[576 * 384];         // qkv_w  hi|lo
__device__ __nv_bfloat16 g_bp[192 * 384];         // proj_w hi|lo
__device__ float g_q[NWIN * HEADS * 64 * 32];     // [win][head][t][d] (scaled)
__device__ float g_k[NWIN * HEADS * 64 * 32];
__device__ float g_v[NWIN * HEADS * 64 * 32];
__device__ float g_ao[NWIN * 64 * DIM];           // [win][t][c]

// ---------------- helpers ---------------------------------------------------
__device__ __forceinline__ uint32_t smem_u32(const void* p) {
    uint32_t a;
    asm("{ .reg .u64 t; cvta.to.shared.u64 t, %1; cvt.u32.u64 %0, t; }" : "=r"(a) : "l"(p));
    return a;
}
__device__ __forceinline__ void ldm_x4(uint32_t addr, uint32_t* r) {
    asm volatile("ldmatrix.sync.aligned.m8n8.x4.shared.b16 {%0,%1,%2,%3}, [%4];"
                 : "=r"(r[0]), "=r"(r[1]), "=r"(r[2]), "=r"(r[3]) : "r"(addr));
}
__device__ __forceinline__ void mma16816(float* acc, const uint32_t* a, uint32_t b0, uint32_t b1) {
    asm volatile("mma.sync.aligned.m16n8k16.row.col.f32.bf16.bf16.f32 "
                 "{%0,%1,%2,%3}, {%4,%5,%6,%7}, {%8,%9}, {%0,%1,%2,%3};"
                 : "+f"(acc[0]), "+f"(acc[1]), "+f"(acc[2]), "+f"(acc[3])
                 : "r"(a[0]), "r"(a[1]), "r"(a[2]), "r"(a[3]), "r"(b0), "r"(b1));
}

// 36-step split-K mainloop: acc[i][j] = warp 32x32 tile (i: 16-row half, j: n8)
__device__ __forceinline__ void gemm_split(uint32_t sb, int wm, int wn, int lane,
                                           float acc[2][4][4]) {
    const int sub = lane >> 3, r8 = lane & 7;
    const int arow0 = wm * 32 + ((sub & 1) << 3) + r8;
    const int akoff = (sub >> 1) << 3;
    const int bn0   = wn * 32 + ((sub >> 1) << 3) + r8;
    const int bkoff = (sub & 1) << 3;

    #pragma unroll
    for (int s = 0; s < 3; s++) {
        const uint32_t Ab = sb + ((s == 1) ? AL_B : AH_B) + (uint32_t)(arow0 * LDA + akoff) * 2;
        const uint32_t Bb = sb + ((s == 2) ? BL_B : BH_B) + (uint32_t)(bn0 * LDB + bkoff) * 2;
        #pragma unroll
        for (int k16 = 0; k16 < 12; k16++) {
            uint32_t a0[4], a1[4], p[4], q[4];
            ldm_x4(Ab + k16 * 32, a0);                   // rows wm*32+0..15
            ldm_x4(Ab + 16 * LDA * 2 + k16 * 32, a1);    // rows +16..31
            ldm_x4(Bb + k16 * 32, p);                    // n-tiles 0,1
            ldm_x4(Bb + 16 * LDB * 2 + k16 * 32, q);     // n-tiles 2,3
            mma16816(acc[0][0], a0, p[0], p[1]);
            mma16816(acc[0][1], a0, p[2], p[3]);
            mma16816(acc[0][2], a0, q[0], q[1]);
            mma16816(acc[0][3], a0, q[2], q[3]);
            mma16816(acc[1][0], a1, p[0], p[1]);
            mma16816(acc[1][1], a1, p[2], p[3]);
            mma16816(acc[1][2], a1, q[0], q[1]);
            mma16816(acc[1][3], a1, q[2], q[3]);
        }
    }
}

// ---------------- weight split prep -----------------------------------------
__global__ void prep_bq_kernel(const float* __restrict__ w) {   // [576][192]
    int i = blockIdx.x * 256 + threadIdx.x;
    if (i < 576 * 192) {
        int n = i / 192, k = i - n * 192;
        float f = w[i];
        __nv_bfloat16 hi = __float2bfloat16(f);
        g_bq[n * 384 + k]       = hi;
        g_bq[n * 384 + 192 + k] = __float2bfloat16(f - __bfloat162float(hi));
    }
}
__global__ void prep_bp_kernel(const float* __restrict__ w) {   // [192][192]
    int i = blockIdx.x * 256 + threadIdx.x;
    if (i < 192 * 192) {
        int n = i / 192, k = i - n * 192;
        float f = w[i];
        __nv_bfloat16 hi = __float2bfloat16(f);
        g_bp[n * 384 + k]       = hi;
        g_bp[n * 384 + 192 + k] = __float2bfloat16(f - __bfloat162float(hi));
    }
}

// ---------------- QKV GEMM (mma.sync) ----------------------------------------
__global__ __launch_bounds__(256, 1)
void qkv_mma_kernel(const float* __restrict__ x, const float* __restrict__ qkv_b) {
    extern __shared__ __align__(16) __nv_bfloat16 sm[];
    __nv_bfloat16* Ah = sm;                 // [128][200]
    __nv_bfloat16* Al = sm + 25600;
    __nv_bfloat16* Bh = sm + 51200;         // [64][200]
    __nv_bfloat16* Bl = sm + 64000;
    const uint32_t sb = smem_u32(sm);

    const int tid = threadIdx.x;
    const int warp = tid >> 5, lane = tid & 31;
    const int wm = warp >> 1, wn = warp & 1;
    const int win0 = blockIdx.x * 2;

    // gather shifted-window x -> Ah/Al
    for (int idx = tid; idx < 192 * 128; idx += 256) {
        int k = idx >> 7, r = idx & 127;
        int win = win0 + (r >> 6), t = r & 63;
        int wi = win & 1023, wh = wi >> 5, wc = wi & 31, bb = win >> 10;
        int h = (wh * 8 + (t >> 3) + SHIFT) & 255;
        int w = (wc * 8 + (t & 7) + SHIFT) & 255;
        float f = x[(bb * 192 + k) * 65536 + (h << 8) + w];
        __nv_bfloat16 hi = __float2bfloat16(f);
        Ah[r * LDA + k] = hi;
        Al[r * LDA + k] = __float2bfloat16(f - __bfloat162float(hi));
    }

    for (int nt = 0; nt < 9; nt++) {
        __syncthreads();                      // protect B from previous iter reads
        for (int idx = tid; idx < 64 * 96; idx += 256) {
            int n = idx / 96, kp = idx - n * 96;
            const uint32_t* src = (const uint32_t*)(g_bq + (nt * 64 + n) * 384);
            ((uint32_t*)(Bh + n * LDB))[kp] = src[kp];
            ((uint32_t*)(Bl + n * LDB))[kp] = src[96 + kp];
        }
        __syncthreads();                      // also covers A on first iter

        float acc[2][4][4];
        #pragma unroll
        for (int i = 0; i < 2; i++)
            #pragma unroll
            for (int j = 0; j < 4; j++)
                acc[i][j][0] = acc[i][j][1] = acc[i][j][2] = acc[i][j][3] = 0.f;

        gemm_split(sb, wm, wn, lane, acc);

        const int sel = nt / 3;               // 0=q 1=k 2=v
        float* dst = (sel == 0) ? g_q : ((sel == 1) ? g_k : g_v);
        const int r0 = wm * 32 + (lane >> 2);
        #pragma unroll
        for (int i = 0; i < 2; i++) {
            #pragma unroll
            for (int j = 0; j < 4; j++) {
                int n  = nt * 64 + wn * 32 + j * 8 + 2 * (lane & 3);
                int nn = n - sel * 192;
                int head = nn >> 5, d = nn & 31;
                float b0 = __ldg(qkv_b + n), b1 = __ldg(qkv_b + n + 1);
                #pragma unroll
                for (int half = 0; half < 2; half++) {
                    int row = r0 + i * 16 + half * 8;
                    int win = win0 + (row >> 6), t = row & 63;
                    float v0 = acc[i][j][half * 2 + 0] + b0;
                    float v1 = acc[i][j][half * 2 + 1] + b1;
                    if (sel == 0) { v0 *= QSCALE; v1 *= QSCALE; }
                    *(float2*)&dst[((win * 6 + head) * 64 + t) * 32 + d] = make_float2(v0, v1);
                }
            }
        }
    }
}

// ---------------- attention (fp32 SIMT, round-1 known-good) ------------------
__global__ __launch_bounds__(256, 4)
void attn_kernel(const float* __restrict__ rpb) {
    __shared__ __align__(16) float qs[32 * 68];
    __shared__ __align__(16) float ks[32 * 68];
    __shared__ __align__(16) float vs[64 * 32];
    __shared__ __align__(16) float ss[64 * 68];
    __shared__ float rb[225];

    const int bid  = blockIdx.x;
    const int win  = bid / 6;
    const int head = bid - win * 6;
    const int wi   = win & 1023;
    const int wh   = wi >> 5;
    const int wc   = wi & 31;
    const int tid  = threadIdx.x;

    const int base = (win * HEADS + head) * 64 * 32;
    for (int i = tid; i < 64 * 32; i += 256) {
        int t = i >> 5, d = i & 31;
        qs[d * 68 + t] = g_q[base + i];
        ks[d * 68 + t] = g_k[base + i];
        vs[i]          = g_v[base + i];
    }
    for (int i = tid; i < 225; i += 256) rb[i] = rpb[i * 6 + head];
    __syncthreads();

    const int tx = tid & 15, ty = tid >> 4;
    const int m0 = ty * 4, n0 = tx * 4;
    float acc[4][4] = {};
    #pragma unroll
    for (int d = 0; d < 32; d++) {
        float4 a  = *(const float4*)(qs + d * 68 + m0);
        float4 bv = *(const float4*)(ks + d * 68 + n0);
        acc[0][0] += a.x * bv.x; acc[0][1] += a.x * bv.y; acc[0][2] += a.x * bv.z; acc[0][3] += a.x * bv.w;
        acc[1][0] += a.y * bv.x; acc[1][1] += a.y * bv.y; acc[1][2] += a.y * bv.z; acc[1][3] += a.y * bv.w;
        acc[2][0] += a.z * bv.x; acc[2][1] += a.z * bv.y; acc[2][2] += a.z * bv.z; acc[2][3] += a.z * bv.w;
        acc[3][0] += a.w * bv.x; acc[3][1] += a.w * bv.y; acc[3][2] += a.w * bv.z; acc[3][3] += a.w * bv.w;
    }

    int lq[4], lk[4];
    #pragma unroll
    for (int i = 0; i < 4; i++) {
        int m = m0 + i; int ti = m >> 3, tj = m & 7;
        lq[i] = ((wh == 31) ? ((ti < 4) ? 1 : 2) : 0) * 3
              + ((wc == 31) ? ((tj < 4) ? 1 : 2) : 0);
        int n = n0 + i; int ki = n >> 3, kj = n & 7;
        lk[i] = ((wh == 31) ? ((ki < 4) ? 1 : 2) : 0) * 3
              + ((wc == 31) ? ((kj < 4) ? 1 : 2) : 0);
    }
    #pragma unroll
    for (int i = 0; i < 4; i++) {
        int m = m0 + i;
        #pragma unroll
        for (int j = 0; j < 4; j++) {
            int n = n0 + j;
            int rel = ((m >> 3) - (n >> 3) + 7) * 15 + ((m & 7) - (n & 7) + 7);
            float v = acc[i][j] + rb[rel];
            if (lq[i] != lk[j]) v -= 100.0f;
            ss[m * 68 + n] = v;
        }
    }
    __syncthreads();

    {
        const int row = tid >> 2, l4 = tid & 3;
        float vals[16];
        float mx = -1e30f;
        #pragma unroll
        for (int t = 0; t < 16; t++) {
            vals[t] = ss[row * 68 + l4 + 4 * t];
            mx = fmaxf(mx, vals[t]);
        }
        mx = fmaxf(mx, __shfl_xor_sync(0xffffffffu, mx, 1));
        mx = fmaxf(mx, __shfl_xor_sync(0xffffffffu, mx, 2));
        float sum = 0.f;
        #pragma unroll
        for (int t = 0; t < 16; t++) { vals[t] = __expf(vals[t] - mx); sum += vals[t]; }
        sum += __shfl_xor_sync(0xffffffffu, sum, 1);
        sum += __shfl_xor_sync(0xffffffffu, sum, 2);
        float inv = 1.0f / sum;
        #pragma unroll
        for (int t = 0; t < 16; t++) ss[row * 68 + l4 + 4 * t] = vals[t] * inv;
    }
    __syncthreads();

    const int n0b = tx * 2;
    float o[4][2] = {};
    for (int c = 0; c < 64; c++) {
        float b0 = vs[c * 32 + n0b];
        float b1 = vs[c * 32 + n0b + 1];
        #pragma unroll
        for (int i = 0; i < 4; i++) {
            float a = ss[(m0 + i) * 68 + c];
            o[i][0] += a * b0;
            o[i][1] += a * b1;
        }
    }
    #pragma unroll
    for (int i = 0; i < 4; i++)
        #pragma unroll
        for (int j = 0; j < 2; j++)
            g_ao[(win * 64 + m0 + i) * DIM + head * 32 + n0b + j] = o[i][j];
}

// ---------------- proj GEMM (mma.sync) ---------------------------------------
__global__ __launch_bounds__(256, 1)
void proj_mma_kernel(const float* __restrict__ proj_b, float* __restrict__ out) {
    extern __shared__ __align__(16) __nv_bfloat16 sm[];
    __nv_bfloat16* Ah = sm;
    __nv_bfloat16* Al = sm + 25600;
    __nv_bfloat16* Bh = sm + 51200;
    __nv_bfloat16* Bl = sm + 64000;
    const uint32_t sb = smem_u32(sm);

    const int tid = threadIdx.x;
    const int warp = tid >> 5, lane = tid & 31;
    const int wm = warp >> 1, wn = warp & 1;
    const int win0 = blockIdx.x * 2;

    // A = attention output rows (coalesced read) -> Ah/Al
    const float* ao = g_ao + win0 * (64 * DIM);
    for (int idx = tid; idx < 192 * 128; idx += 256) {
        int r = idx / 192, k = idx - r * 192;
        float f = ao[idx];
        __nv_bfloat16 hi = __float2bfloat16(f);
        Ah[r * LDA + k] = hi;
        Al[r * LDA + k] = __float2bfloat16(f - __bfloat162float(hi));
    }

    for (int nt = 0; nt < 3; nt++) {
        __syncthreads();
        for (int idx = tid; idx < 64 * 96; idx += 256) {
            int n = idx / 96, kp = idx - n * 96;
            const uint32_t* src = (const uint32_t*)(g_bp + (nt * 64 + n) * 384);
            ((uint32_t*)(Bh + n * LDB))[kp] = src[kp];
            ((uint32_t*)(Bl + n * LDB))[kp] = src[96 + kp];
        }
        __syncthreads();

        float acc[2][4][4];
        #pragma unroll
        for (int i = 0; i < 2; i++)
            #pragma unroll
            for (int j = 0; j < 4; j++)
                acc[i][j][0] = acc[i][j][1] = acc[i][j][2] = acc[i][j][3] = 0.f;

        gemm_split(sb, wm, wn, lane, acc);

        const int r0 = wm * 32 + (lane >> 2);
        #pragma unroll
        for (int i = 0; i < 2; i++) {
            #pragma unroll
            for (int j = 0; j < 4; j++) {
                int c = nt * 64 + wn * 32 + j * 8 + 2 * (lane & 3);
                float b0 = __ldg(proj_b + c), b1 = __ldg(proj_b + c + 1);
                #pragma unroll
                for (int half = 0; half < 2; half++) {
                    int row = r0 + i * 16 + half * 8;
                    int win = win0 + (row >> 6), t = row & 63;
                    int wi = win & 1023, wh = wi >> 5, wc = wi & 31, bb = win >> 10;
                    int h = (wh * 8 + (t >> 3) + SHIFT) & 255;   // reverse shift
                    int w = (wc * 8 + (t & 7) + SHIFT) & 255;
                    int pix = (h << 8) + w;
                    out[(bb * 192 + c) * 65536 + pix]       = acc[i][j][half * 2 + 0] + b0;
                    out[(bb * 192 + c + 1) * 65536 + pix]   = acc[i][j][half * 2 + 1] + b1;
                }
            }
        }
    }
}

// ---------------- launch ------------------------------------------------------
extern "C" void kernel_launch(void* const* d_in, const int* in_sizes, int n_in,
                              void* d_out, int out_size) {
    const float* x      = (const float*)d_in[0];
    const float* qkv_w  = (const float*)d_in[1];
    const float* qkv_b  = (const float*)d_in[2];
    const float* proj_w = (const float*)d_in[3];
    const float* proj_b = (const float*)d_in[4];
    const float* rpb    = (const float*)d_in[5];
    float* out = (float*)d_out;

    cudaFuncSetAttribute(qkv_mma_kernel,  cudaFuncAttributeMaxDynamicSharedMemorySize, SM_BYTES);
    cudaFuncSetAttribute(proj_mma_kernel, cudaFuncAttributeMaxDynamicSharedMemorySize, SM_BYTES);

    prep_bq_kernel<<<(576 * 192 + 255) / 256, 256>>>(qkv_w);
    prep_bp_kernel<<<(192 * 192 + 255) / 256, 256>>>(proj_w);
    qkv_mma_kernel<<<NWIN / 2, 256, SM_BYTES>>>(x, qkv_b);
    attn_kernel<<<NWIN * HEADS, 256>>>(rpb);
    proj_mma_kernel<<<NWIN / 2, 256, SM_BYTES>>>(proj_b, out);
}

// round 6
// speedup vs baseline: 2.0847x; 1.1186x over previous
#include <cuda_runtime.h>
#include <cuda_bf16.h>
#include <cstdint>

// ---------------------------------------------------------------------------
// Swin shifted-window attention, GB300 (compute_103: tensor pipe via mma.sync).
//   B=4, DIM=192, HEADS=6, HD=32, H=W=256, WS=8, SS=4 -> 4096 windows x 64 tok
// Round-6:
//   - qkv/proj GEMMs: bf16 split-K (C = Ah*Bh + Al*Bh + Ah*Bl), M=128/CTA,
//     now with cp.async DOUBLE-BUFFERED B staging (latency fully overlapped).
//   - attention: PV loop rewritten as transposed-P split-k GEMM with float4
//     smem traffic; P^T overlays the dead q/k smem (no occupancy loss).
// ---------------------------------------------------------------------------

#define DIM    192
#define HEADS  6
#define SHIFT  4
#define NWIN   4096
#define QSCALE 0.17677669529663687f

#define LDA 200              // bf16 elems per A row (400B pitch, conflict-free)
#define LDB 200
// smem byte offsets
#define AH_B 0               // Ah [128][200]
#define AL_B 51200           // Al [128][200]
#define B0_B 102400          // buf0: Bh | Bl (25600 each)
#define B1_B 153600          // buf1: Bh | Bl
#define SM_BYTES 204800

// ---------------- scratch ---------------------------------------------------
__device__ __nv_bfloat16 g_bq[576 * 384];         // qkv_w  hi|lo per row
__device__ __nv_bfloat16 g_bp[192 * 384];         // proj_w hi|lo per row
__device__ float g_q[NWIN * HEADS * 64 * 32];     // [win][head][t][d] (scaled)
__device__ float g_k[NWIN * HEADS * 64 * 32];
__device__ float g_v[NWIN * HEADS * 64 * 32];
__device__ float g_ao[NWIN * 64 * DIM];           // [win][t][c]

// ---------------- helpers ---------------------------------------------------
__device__ __forceinline__ uint32_t smem_u32(const void* p) {
    uint32_t a;
    asm("{ .reg .u64 t; cvta.to.shared.u64 t, %1; cvt.u32.u64 %0, t; }" : "=r"(a) : "l"(p));
    return a;
}
__device__ __forceinline__ void ldm_x4(uint32_t addr, uint32_t* r) {
    asm volatile("ldmatrix.sync.aligned.m8n8.x4.shared.b16 {%0,%1,%2,%3}, [%4];"
                 : "=r"(r[0]), "=r"(r[1]), "=r"(r[2]), "=r"(r[3]) : "r"(addr));
}
__device__ __forceinline__ void mma16816(float* acc, const uint32_t* a, uint32_t b0, uint32_t b1) {
    asm volatile("mma.sync.aligned.m16n8k16.row.col.f32.bf16.bf16.f32 "
                 "{%0,%1,%2,%3}, {%4,%5,%6,%7}, {%8,%9}, {%0,%1,%2,%3};"
                 : "+f"(acc[0]), "+f"(acc[1]), "+f"(acc[2]), "+f"(acc[3])
                 : "r"(a[0]), "r"(a[1]), "r"(a[2]), "r"(a[3]), "r"(b0), "r"(b1));
}
#define CP_ASYNC16(dst, src) \
    asm volatile("cp.async.cg.shared.global [%0], [%1], 16;" :: "r"(dst), "l"(src))
#define CP_COMMIT()  asm volatile("cp.async.commit_group;" ::: "memory")
#define CP_WAIT(N)   asm volatile("cp.async.wait_group %0;" :: "n"(N) : "memory")

// 36-step split-K mainloop: warp computes 32x32; acc[i][j] (i: 16-row, j: n8)
__device__ __forceinline__ void gemm_split(uint32_t sb, uint32_t bh_off,
                                           int wm, int wn, int lane,
                                           float acc[2][4][4]) {
    const int sub = lane >> 3, r8 = lane & 7;
    const int arow0 = wm * 32 + ((sub & 1) << 3) + r8;
    const int akoff = (sub >> 1) << 3;
    const int bn0   = wn * 32 + ((sub >> 1) << 3) + r8;
    const int bkoff = (sub & 1) << 3;
    const uint32_t bl_off = bh_off + 25600;

    #pragma unroll
    for (int s = 0; s < 3; s++) {
        const uint32_t Ab = sb + ((s == 1) ? AL_B : AH_B) + (uint32_t)(arow0 * LDA + akoff) * 2;
        const uint32_t Bb = sb + ((s == 2) ? bl_off : bh_off) + (uint32_t)(bn0 * LDB + bkoff) * 2;
        #pragma unroll
        for (int k16 = 0; k16 < 12; k16++) {
            uint32_t a0[4], a1[4], p[4], q[4];
            ldm_x4(Ab + k16 * 32, a0);
            ldm_x4(Ab + 16 * LDA * 2 + k16 * 32, a1);
            ldm_x4(Bb + k16 * 32, p);
            ldm_x4(Bb + 16 * LDB * 2 + k16 * 32, q);
            mma16816(acc[0][0], a0, p[0], p[1]);
            mma16816(acc[0][1], a0, p[2], p[3]);
            mma16816(acc[0][2], a0, q[0], q[1]);
            mma16816(acc[0][3], a0, q[2], q[3]);
            mma16816(acc[1][0], a1, p[0], p[1]);
            mma16816(acc[1][1], a1, p[2], p[3]);
            mma16816(acc[1][2], a1, q[0], q[1]);
            mma16816(acc[1][3], a1, q[2], q[3]);
        }
    }
}

// stage one 64-row B tile (hi+lo) into buffer via cp.async (no commit here)
__device__ __forceinline__ void stage_B(uint32_t sb, uint32_t buf_off,
                                        const __nv_bfloat16* wsplit,
                                        int nt, int tid) {
    const char* src_base = (const char*)wsplit + (size_t)nt * 64 * 768;
    #pragma unroll
    for (int u = 0; u < 12; u++) {
        int idx = tid + u * 256;              // 3072 chunks of 16B
        int n = idx / 48, rem = idx - n * 48;
        int half = rem >> 4 >= 0 ? (rem / 24) : 0;   // 0 = hi, 1 = lo
        int c = rem - half * 24;
        uint32_t dst = sb + buf_off + (uint32_t)half * 25600 + (uint32_t)(n * 400 + c * 16);
        const char* src = src_base + n * 768 + half * 384 + c * 16;
        CP_ASYNC16(dst, src);
    }
}

// ---------------- weight split prep -----------------------------------------
__global__ void prep_bq_kernel(const float* __restrict__ w) {   // [576][192]
    int i = blockIdx.x * 256 + threadIdx.x;
    if (i < 576 * 192) {
        int n = i / 192, k = i - n * 192;
        float f = w[i];
        __nv_bfloat16 hi = __float2bfloat16(f);
        g_bq[n * 384 + k]       = hi;
        g_bq[n * 384 + 192 + k] = __float2bfloat16(f - __bfloat162float(hi));
    }
}
__global__ void prep_bp_kernel(const float* __restrict__ w) {   // [192][192]
    int i = blockIdx.x * 256 + threadIdx.x;
    if (i < 192 * 192) {
        int n = i / 192, k = i - n * 192;
        float f = w[i];
        __nv_bfloat16 hi = __float2bfloat16(f);
        g_bp[n * 384 + k]       = hi;
        g_bp[n * 384 + 192 + k] = __float2bfloat16(f - __bfloat162float(hi));
    }
}

// ---------------- QKV GEMM (mma.sync, double-buffered B) ---------------------
__global__ __launch_bounds__(256, 1)
void qkv_mma_kernel(const float* __restrict__ x, const float* __restrict__ qkv_b) {
    extern __shared__ __align__(16) __nv_bfloat16 sm[];
    __nv_bfloat16* Ah = sm;
    __nv_bfloat16* Al = sm + 25600;
    const uint32_t sb = smem_u32(sm);

    const int tid = threadIdx.x;
    const int warp = tid >> 5, lane = tid & 31;
    const int wm = warp >> 1, wn = warp & 1;
    const int win0 = blockIdx.x * 2;

    // prefetch tile-0 B first so it overlaps the A gather
    stage_B(sb, B0_B, g_bq, 0, tid);
    CP_COMMIT();

    // gather shifted-window x -> Ah/Al
    for (int idx = tid; idx < 192 * 128; idx += 256) {
        int k = idx >> 7, r = idx & 127;
        int win = win0 + (r >> 6), t = r & 63;
        int wi = win & 1023, wh = wi >> 5, wc = wi & 31, bb = win >> 10;
        int h = (wh * 8 + (t >> 3) + SHIFT) & 255;
        int w = (wc * 8 + (t & 7) + SHIFT) & 255;
        float f = x[(bb * 192 + k) * 65536 + (h << 8) + w];
        __nv_bfloat16 hi = __float2bfloat16(f);
        Ah[r * LDA + k] = hi;
        Al[r * LDA + k] = __float2bfloat16(f - __bfloat162float(hi));
    }

    for (int nt = 0; nt < 9; nt++) {
        const uint32_t cur = (nt & 1) ? B1_B : B0_B;
        if (nt + 1 < 9) {
            stage_B(sb, (nt & 1) ? B0_B : B1_B, g_bq, nt + 1, tid);
            CP_COMMIT();
            CP_WAIT(1);                // current tile's group complete
        } else {
            CP_WAIT(0);
        }
        __syncthreads();               // B visible + A ready (first iter)

        float acc[2][4][4];
        #pragma unroll
        for (int i = 0; i < 2; i++)
            #pragma unroll
            for (int j = 0; j < 4; j++)
                acc[i][j][0] = acc[i][j][1] = acc[i][j][2] = acc[i][j][3] = 0.f;

        gemm_split(sb, cur, wm, wn, lane, acc);

        const int sel = nt / 3;               // 0=q 1=k 2=v
        float* dst = (sel == 0) ? g_q : ((sel == 1) ? g_k : g_v);
        const int r0 = wm * 32 + (lane >> 2);
        #pragma unroll
        for (int i = 0; i < 2; i++) {
            #pragma unroll
            for (int j = 0; j < 4; j++) {
                int n  = nt * 64 + wn * 32 + j * 8 + 2 * (lane & 3);
                int nn = n - sel * 192;
                int head = nn >> 5, d = nn & 31;
                float b0 = __ldg(qkv_b + n), b1 = __ldg(qkv_b + n + 1);
                #pragma unroll
                for (int half = 0; half < 2; half++) {
                    int row = r0 + i * 16 + half * 8;
                    int win = win0 + (row >> 6), t = row & 63;
                    float v0 = acc[i][j][half * 2 + 0] + b0;
                    float v1 = acc[i][j][half * 2 + 1] + b1;
                    if (sel == 0) { v0 *= QSCALE; v1 *= QSCALE; }
                    *(float2*)&dst[((win * 6 + head) * 64 + t) * 32 + d] = make_float2(v0, v1);
                }
            }
        }
        __syncthreads();               // done reading cur before it is re-staged
    }
}

// ---------------- attention (fp32 SIMT, transposed-P PV) ---------------------
__global__ __launch_bounds__(256, 4)
void attn_kernel(const float* __restrict__ rpb) {
    __shared__ __align__(16) float qk[2 * 32 * 68];  // qs|ks, later P^T [k][q]
    __shared__ __align__(16) float vs[64 * 32];      // v [k][d]
    __shared__ __align__(16) float ss[64 * 68];      // scores, later partials
    __shared__ float rb[225];
    float* qs = qk;
    float* ks = qk + 32 * 68;
    float* st = qk;                                   // P^T overlay [64][68]

    const int bid  = blockIdx.x;
    const int win  = bid / 6;
    const int head = bid - win * 6;
    const int wi   = win & 1023;
    const int wh   = wi >> 5;
    const int wc   = wi & 31;
    const int tid  = threadIdx.x;

    const int base = (win * HEADS + head) * 64 * 32;
    for (int i = tid; i < 64 * 32; i += 256) {
        int t = i >> 5, d = i & 31;
        qs[d * 68 + t] = g_q[base + i];
        ks[d * 68 + t] = g_k[base + i];
        vs[i]          = g_v[base + i];
    }
    for (int i = tid; i < 225; i += 256) rb[i] = rpb[i * 6 + head];
    __syncthreads();

    // S = q^T k
    const int tx = tid & 15, ty = tid >> 4;
    const int m0 = ty * 4, n0 = tx * 4;
    float acc[4][4] = {};
    #pragma unroll
    for (int d = 0; d < 32; d++) {
        float4 a  = *(const float4*)(qs + d * 68 + m0);
        float4 bv = *(const float4*)(ks + d * 68 + n0);
        acc[0][0] += a.x * bv.x; acc[0][1] += a.x * bv.y; acc[0][2] += a.x * bv.z; acc[0][3] += a.x * bv.w;
        acc[1][0] += a.y * bv.x; acc[1][1] += a.y * bv.y; acc[1][2] += a.y * bv.z; acc[1][3] += a.y * bv.w;
        acc[2][0] += a.z * bv.x; acc[2][1] += a.z * bv.y; acc[2][2] += a.z * bv.z; acc[2][3] += a.z * bv.w;
        acc[3][0] += a.w * bv.x; acc[3][1] += a.w * bv.y; acc[3][2] += a.w * bv.z; acc[3][3] += a.w * bv.w;
    }

    int lq[4], lk[4];
    #pragma unroll
    for (int i = 0; i < 4; i++) {
        int m = m0 + i; int ti = m >> 3, tj = m & 7;
        lq[i] = ((wh == 31) ? ((ti < 4) ? 1 : 2) : 0) * 3
              + ((wc == 31) ? ((tj < 4) ? 1 : 2) : 0);
        int n = n0 + i; int ki = n >> 3, kj = n & 7;
        lk[i] = ((wh == 31) ? ((ki < 4) ? 1 : 2) : 0) * 3
              + ((wc == 31) ? ((kj < 4) ? 1 : 2) : 0);
    }
    #pragma unroll
    for (int i = 0; i < 4; i++) {
        int m = m0 + i;
        #pragma unroll
        for (int j = 0; j < 4; j++) {
            int n = n0 + j;
            int rel = ((m >> 3) - (n >> 3) + 7) * 15 + ((m & 7) - (n & 7) + 7);
            float v = acc[i][j] + rb[rel];
            if (lq[i] != lk[j]) v -= 100.0f;
            ss[m * 68 + n] = v;
        }
    }
    __syncthreads();   // scores complete; qs/ks dead from here

    // softmax (4 lanes/row), write normalized P TRANSPOSED into st[k][q]
    {
        const int row = tid >> 2, l4 = tid & 3;
        float vals[16];
        float mx = -1e30f;
        #pragma unroll
        for (int t = 0; t < 16; t++) {
            vals[t] = ss[row * 68 + l4 + 4 * t];
            mx = fmaxf(mx, vals[t]);
        }
        mx = fmaxf(mx, __shfl_xor_sync(0xffffffffu, mx, 1));
        mx = fmaxf(mx, __shfl_xor_sync(0xffffffffu, mx, 2));
        float sum = 0.f;
        #pragma unroll
        for (int t = 0; t < 16; t++) { vals[t] = __expf(vals[t] - mx); sum += vals[t]; }
        sum += __shfl_xor_sync(0xffffffffu, sum, 1);
        sum += __shfl_xor_sync(0xffffffffu, sum, 2);
        float inv = 1.0f / sum;
        #pragma unroll
        for (int t = 0; t < 16; t++) st[(l4 + 4 * t) * 68 + row] = vals[t] * inv;
    }
    __syncthreads();

    // O = P V as split-k GEMM: thread = (khalf, m-quad, n-quad); float4 loads
    {
        const int kh = tid >> 7;              // 0/1 -> k in [0,32)/[32,64)
        const int rem = tid & 127;
        const int pm0 = (rem >> 3) * 4;       // 16 m-quads
        const int pn0 = (rem & 7) * 4;        // 8  n-quads
        float o[4][4] = {};
        const int k0 = kh * 32;
        #pragma unroll 8
        for (int k = k0; k < k0 + 32; k++) {
            float4 a = *(const float4*)(st + k * 68 + pm0);
            float4 b = *(const float4*)(vs + k * 32 + pn0);
            o[0][0] += a.x * b.x; o[0][1] += a.x * b.y; o[0][2] += a.x * b.z; o[0][3] += a.x * b.w;
            o[1][0] += a.y * b.x; o[1][1] += a.y * b.y; o[1][2] += a.y * b.z; o[1][3] += a.y * b.w;
            o[2][0] += a.z * b.x; o[2][1] += a.z * b.y; o[2][2] += a.z * b.z; o[2][3] += a.z * b.w;
            o[3][0] += a.w * b.x; o[3][1] += a.w * b.y; o[3][2] += a.w * b.z; o[3][3] += a.w * b.w;
        }
        __syncthreads();   // ss (scores) fully consumed; reuse as partial buffer
        #pragma unroll
        for (int i = 0; i < 4; i++)
            *(float4*)&ss[kh * 2048 + (pm0 + i) * 32 + pn0] =
                make_float4(o[i][0], o[i][1], o[i][2], o[i][3]);
    }
    __syncthreads();

    // reduce the two k-halves and store (float4 all the way)
    {
        const int j = tid * 8;
        const int m = j >> 5, n = j & 31;
        float4 p0 = *(const float4*)&ss[m * 32 + n];
        float4 p1 = *(const float4*)&ss[m * 32 + n + 4];
        float4 q0 = *(const float4*)&ss[2048 + m * 32 + n];
        float4 q1 = *(const float4*)&ss[2048 + m * 32 + n + 4];
        p0.x += q0.x; p0.y += q0.y; p0.z += q0.z; p0.w += q0.w;
        p1.x += q1.x; p1.y += q1.y; p1.z += q1.z; p1.w += q1.w;
        float* dst = &g_ao[(win * 64 + m) * DIM + head * 32 + n];
        *(float4*)dst = p0;
        *(float4*)(dst + 4) = p1;
    }
}

// ---------------- proj GEMM (mma.sync, double-buffered B) --------------------
__global__ __launch_bounds__(256, 1)
void proj_mma_kernel(const float* __restrict__ proj_b, float* __restrict__ out) {
    extern __shared__ __align__(16) __nv_bfloat16 sm[];
    __nv_bfloat16* Ah = sm;
    __nv_bfloat16* Al = sm + 25600;
    const uint32_t sb = smem_u32(sm);

    const int tid = threadIdx.x;
    const int warp = tid >> 5, lane = tid & 31;
    const int wm = warp >> 1, wn = warp & 1;
    const int win0 = blockIdx.x * 2;

    stage_B(sb, B0_B, g_bp, 0, tid);
    CP_COMMIT();

    const float* ao = g_ao + win0 * (64 * DIM);
    for (int idx = tid; idx < 192 * 128; idx += 256) {
        int r = idx / 192, k = idx - r * 192;
        float f = ao[idx];
        __nv_bfloat16 hi = __float2bfloat16(f);
        Ah[r * LDA + k] = hi;
        Al[r * LDA + k] = __float2bfloat16(f - __bfloat162float(hi));
    }

    for (int nt = 0; nt < 3; nt++) {
        const uint32_t cur = (nt & 1) ? B1_B : B0_B;
        if (nt + 1 < 3) {
            stage_B(sb, (nt & 1) ? B0_B : B1_B, g_bp, nt + 1, tid);
            CP_COMMIT();
            CP_WAIT(1);
        } else {
            CP_WAIT(0);
        }
        __syncthreads();

        float acc[2][4][4];
        #pragma unroll
        for (int i = 0; i < 2; i++)
            #pragma unroll
            for (int j = 0; j < 4; j++)
                acc[i][j][0] = acc[i][j][1] = acc[i][j][2] = acc[i][j][3] = 0.f;

        gemm_split(sb, cur, wm, wn, lane, acc);

        const int r0 = wm * 32 + (lane >> 2);
        #pragma unroll
        for (int i = 0; i < 2; i++) {
            #pragma unroll
            for (int j = 0; j < 4; j++) {
                int c = nt * 64 + wn * 32 + j * 8 + 2 * (lane & 3);
                float b0 = __ldg(proj_b + c), b1 = __ldg(proj_b + c + 1);
                #pragma unroll
                for (int half = 0; half < 2; half++) {
                    int row = r0 + i * 16 + half * 8;
                    int win = win0 + (row >> 6), t = row & 63;
                    int wi = win & 1023, wh = wi >> 5, wc = wi & 31, bb = win >> 10;
                    int h = (wh * 8 + (t >> 3) + SHIFT) & 255;
                    int w = (wc * 8 + (t & 7) + SHIFT) & 255;
                    int pix = (h << 8) + w;
                    out[(bb * 192 + c) * 65536 + pix]     = acc[i][j][half * 2 + 0] + b0;
                    out[(bb * 192 + c + 1) * 65536 + pix] = acc[i][j][half * 2 + 1] + b1;
                }
            }
        }
        __syncthreads();
    }
}

// ---------------- launch ------------------------------------------------------
extern "C" void kernel_launch(void* const* d_in, const int* in_sizes, int n_in,
                              void* d_out, int out_size) {
    const float* x      = (const float*)d_in[0];
    const float* qkv_w  = (const float*)d_in[1];
    const float* qkv_b  = (const float*)d_in[2];
    const float* proj_w = (const float*)d_in[3];
    const float* proj_b = (const float*)d_in[4];
    const float* rpb    = (const float*)d_in[5];
    float* out = (float*)d_out;

    cudaFuncSetAttribute(qkv_mma_kernel,  cudaFuncAttributeMaxDynamicSharedMemorySize, SM_BYTES);
    cudaFuncSetAttribute(proj_mma_kernel, cudaFuncAttributeMaxDynamicSharedMemorySize, SM_BYTES);

    prep_bq_kernel<<<(576 * 192 + 255) / 256, 256>>>(qkv_w);
    prep_bp_kernel<<<(192 * 192 + 255) / 256, 256>>>(proj_w);
    qkv_mma_kernel<<<NWIN / 2, 256, SM_BYTES>>>(x, qkv_b);
    attn_kernel<<<NWIN * HEADS, 256>>>(rpb);
    proj_mma_kernel<<<NWIN / 2, 256, SM_BYTES>>>(proj_b, out);
}